// round 1
// baseline (speedup 1.0000x reference)
#include <cuda_runtime.h>
#include <cstdint>

#define N_NODES 50000
#define N_EDGES 800000
#define DIM 128
#define DIM4 (DIM/4)   // 32 float4 per row

// Scratch (allocation-free: __device__ globals)
__device__ float g_h[N_NODES * DIM];     // gemm output (reused both layers)
__device__ float g_z[N_NODES * DIM];     // layer-1 activations
__device__ float g_acc[N_NODES * DIM];   // aggregation accumulator
__device__ float g_deg[N_NODES];
__device__ float g_dinv[N_NODES];
__device__ float g_norm[N_EDGES];

// ---------------------------------------------------------------------------
// degree / norm precompute
// ---------------------------------------------------------------------------
__global__ void k_deg_init(int n) {
    int i = blockIdx.x * blockDim.x + threadIdx.x;
    if (i < n) g_deg[i] = 1.0f;   // self-loop weight
}

__global__ void k_deg(const int* __restrict__ dst, const float* __restrict__ ew, int e) {
    int i = blockIdx.x * blockDim.x + threadIdx.x;
    if (i < e) atomicAdd(&g_deg[dst[i]], ew[i]);
}

__global__ void k_dinv(int n) {
    int i = blockIdx.x * blockDim.x + threadIdx.x;
    if (i < n) g_dinv[i] = rsqrtf(g_deg[i]);   // deg >= 1 always (self loop)
}

__global__ void k_norm(const int* __restrict__ src, const int* __restrict__ dst,
                       const float* __restrict__ ew, int e) {
    int i = blockIdx.x * blockDim.x + threadIdx.x;
    if (i < e) g_norm[i] = g_dinv[src[i]] * ew[i] * g_dinv[dst[i]];
}

// ---------------------------------------------------------------------------
// GEMM: out[n,128] = in[n,128] @ W[128,128]
// W resident in smem (64KB). Block = 256 thr = 8 warps; 32 rows per iter.
// Warp computes 4 rows x 128 cols; lane holds 4 cols x 4 rows in regs.
// ---------------------------------------------------------------------------
__global__ void k_gemm(const float* __restrict__ in, const float* __restrict__ W,
                       float* __restrict__ out, int n) {
    extern __shared__ float smem[];
    float* Ws = smem;                 // [128][128]
    float* xs = smem + DIM * DIM;     // [32][128]

    for (int i = threadIdx.x; i < DIM * DIM4; i += blockDim.x)
        ((float4*)Ws)[i] = ((const float4*)W)[i];
    __syncthreads();

    const int warp = threadIdx.x >> 5;
    const int lane = threadIdx.x & 31;

    for (int row0 = blockIdx.x * 32; row0 < n; row0 += gridDim.x * 32) {
        const int nrows = min(32, n - row0);
        __syncthreads();  // xs reuse fence
        for (int i = threadIdx.x; i < nrows * DIM4; i += blockDim.x)
            ((float4*)xs)[i] = ((const float4*)(in + (size_t)row0 * DIM))[i];
        __syncthreads();

        const int r0 = warp * 4;
        float acc[4][4];
        #pragma unroll
        for (int r = 0; r < 4; r++)
            #pragma unroll
            for (int c = 0; c < 4; c++) acc[r][c] = 0.0f;

        #pragma unroll 4
        for (int k = 0; k < DIM; k++) {
            float4 wv = ((const float4*)(Ws + k * DIM))[lane];
            #pragma unroll
            for (int r = 0; r < 4; r++) {
                float xk = xs[(r0 + r) * DIM + k];
                acc[r][0] = fmaf(xk, wv.x, acc[r][0]);
                acc[r][1] = fmaf(xk, wv.y, acc[r][1]);
                acc[r][2] = fmaf(xk, wv.z, acc[r][2]);
                acc[r][3] = fmaf(xk, wv.w, acc[r][3]);
            }
        }

        #pragma unroll
        for (int r = 0; r < 4; r++) {
            int row = row0 + r0 + r;
            if (row < n)
                ((float4*)(out + (size_t)row * DIM))[lane] =
                    make_float4(acc[r][0], acc[r][1], acc[r][2], acc[r][3]);
        }
    }
}

// ---------------------------------------------------------------------------
// Self-loop init: acc[n,:] = dinv[n]^2 * h[n,:]
// One thread per float4.
// ---------------------------------------------------------------------------
__global__ void k_self(const float* __restrict__ h, float* __restrict__ acc, int n) {
    int i = blockIdx.x * blockDim.x + threadIdx.x;
    if (i < n * DIM4) {
        int node = i >> 5;
        float di = g_dinv[node];
        float s = di * di;
        float4 v = ((const float4*)h)[i];
        ((float4*)acc)[i] = make_float4(v.x * s, v.y * s, v.z * s, v.w * s);
    }
}

// ---------------------------------------------------------------------------
// Edge scatter: acc[dst,:] += norm[e] * h[src,:]
// One warp per edge; lane handles 4 consecutive floats via vector RED.
// ---------------------------------------------------------------------------
__global__ void k_scatter(const int* __restrict__ src, const int* __restrict__ dst,
                          const float* __restrict__ h, float* __restrict__ acc, int e) {
    int t = blockIdx.x * blockDim.x + threadIdx.x;
    int edge = t >> 5;
    int lane = t & 31;
    if (edge < e) {
        float nrm = g_norm[edge];
        int s = src[edge];
        int d = dst[edge];
        float4 hv = ((const float4*)(h + (size_t)s * DIM))[lane];
        float* p = acc + (size_t)d * DIM + lane * 4;
        asm volatile("red.global.add.v4.f32 [%0], {%1, %2, %3, %4};"
                     :: "l"(p), "f"(hv.x * nrm), "f"(hv.y * nrm),
                        "f"(hv.z * nrm), "f"(hv.w * nrm)
                     : "memory");
    }
}

// ---------------------------------------------------------------------------
// Bias + ReLU: out = relu(acc + b)
// ---------------------------------------------------------------------------
__global__ void k_finish(const float* __restrict__ acc, const float* __restrict__ b,
                         float* __restrict__ out, int n) {
    int i = blockIdx.x * blockDim.x + threadIdx.x;
    if (i < n * DIM4) {
        float4 a = ((const float4*)acc)[i];
        float4 bv = ((const float4*)b)[i & 31];
        float4 o;
        o.x = fmaxf(a.x + bv.x, 0.0f);
        o.y = fmaxf(a.y + bv.y, 0.0f);
        o.z = fmaxf(a.z + bv.z, 0.0f);
        o.w = fmaxf(a.w + bv.w, 0.0f);
        ((float4*)out)[i] = o;
    }
}

// ---------------------------------------------------------------------------
// launch
// ---------------------------------------------------------------------------
extern "C" void kernel_launch(void* const* d_in, const int* in_sizes, int n_in,
                              void* d_out, int out_size) {
    const float* x   = (const float*)d_in[0];
    const int*   ei  = (const int*)d_in[1];      // [2, E]: src then dst
    const float* ew  = (const float*)d_in[2];
    const float* W1  = (const float*)d_in[3];
    const float* b1  = (const float*)d_in[4];
    const float* W2  = (const float*)d_in[5];
    const float* b2  = (const float*)d_in[6];
    float* out = (float*)d_out;

    const int n = in_sizes[0] / DIM;
    const int e = in_sizes[2];
    const int* src = ei;
    const int* dst = ei + e;

    const int T = 256;
    const int gN  = (n + T - 1) / T;
    const int gE  = (e + T - 1) / T;
    const int gNV = (n * DIM4 + T - 1) / T;        // node*float4 grid
    const int gEW = ((e * 32) + T - 1) / T;        // warp-per-edge grid

    static bool smem_set = false;  // attribute setting is idempotent + host-side only
    const int GEMM_SMEM = (DIM * DIM + 32 * DIM) * sizeof(float);  // 80KB
    if (!smem_set) {
        cudaFuncSetAttribute(k_gemm, cudaFuncAttributeMaxDynamicSharedMemorySize, GEMM_SMEM);
        smem_set = true;
    }
    const int GEMM_GRID = 296;  // ~2 blocks/SM

    float* g_h_p;    cudaGetSymbolAddress((void**)&g_h_p, g_h);
    float* g_z_p;    cudaGetSymbolAddress((void**)&g_z_p, g_z);
    float* g_acc_p;  cudaGetSymbolAddress((void**)&g_acc_p, g_acc);

    // --- degree / norm (same for both layers) ---
    k_deg_init<<<gN, T>>>(n);
    k_deg<<<gE, T>>>(dst, ew, e);
    k_dinv<<<gN, T>>>(n);
    k_norm<<<gE, T>>>(src, dst, ew, e);

    // --- layer 1 ---
    k_gemm<<<GEMM_GRID, T, GEMM_SMEM>>>(x, W1, g_h_p, n);
    k_self<<<gNV, T>>>(g_h_p, g_acc_p, n);
    k_scatter<<<gEW, T>>>(src, dst, g_h_p, g_acc_p, e);
    k_finish<<<gNV, T>>>(g_acc_p, b1, g_z_p, n);

    // --- layer 2 ---
    k_gemm<<<GEMM_GRID, T, GEMM_SMEM>>>(g_z_p, W2, g_h_p, n);
    k_self<<<gNV, T>>>(g_h_p, g_acc_p, n);
    k_scatter<<<gEW, T>>>(src, dst, g_h_p, g_acc_p, e);
    k_finish<<<gNV, T>>>(g_acc_p, b2, out, n);
}

// round 2
// speedup vs baseline: 1.3463x; 1.3463x over previous
#include <cuda_runtime.h>
#include <cstdint>

#define N_NODES 50000
#define N_EDGES 800000
#define DIM 128
#define DIM4 (DIM/4)   // 32 float4 per row

// Scratch (allocation-free: __device__ globals)
__device__ float g_h[N_NODES * DIM];       // gemm output (reused both layers)
__device__ float g_z[N_NODES * DIM];       // layer-1 activations
__device__ float g_deg[N_NODES];
__device__ float g_dinv[N_NODES];
__device__ int   g_cnt[N_NODES];           // in-degree (edge count) per dst
__device__ int   g_cursor[N_NODES];        // placement cursor for reorder
__device__ int   g_rowstart[N_NODES + 1];  // CSR row offsets (by dst)
__device__ int2  g_edges[N_EDGES];         // {src, __float_as_int(norm)} sorted by dst

// ---------------------------------------------------------------------------
// init: deg=1 (self loop), cnt=0, cursor=0
// ---------------------------------------------------------------------------
__global__ void k_init(int n) {
    int i = blockIdx.x * blockDim.x + threadIdx.x;
    if (i < n) { g_deg[i] = 1.0f; g_cnt[i] = 0; g_cursor[i] = 0; }
}

// histogram + weighted degree in one pass over edges
__global__ void k_count(const int* __restrict__ dst, const float* __restrict__ ew, int e) {
    int i = blockIdx.x * blockDim.x + threadIdx.x;
    if (i < e) {
        int d = dst[i];
        atomicAdd(&g_deg[d], ew[i]);
        atomicAdd(&g_cnt[d], 1);
    }
}

__global__ void k_dinv(int n) {
    int i = blockIdx.x * blockDim.x + threadIdx.x;
    if (i < n) g_dinv[i] = rsqrtf(g_deg[i]);   // deg >= 1 always (self loop)
}

// ---------------------------------------------------------------------------
// single-block exclusive scan of g_cnt[0..n) -> g_rowstart (n+1 entries)
// ---------------------------------------------------------------------------
__global__ void k_scan(int n) {
    __shared__ int warpsums[32];
    __shared__ int carry_s;
    if (threadIdx.x == 0) carry_s = 0;
    __syncthreads();
    const int lane = threadIdx.x & 31;
    const int warp = threadIdx.x >> 5;
    for (int base = 0; base < n; base += 1024) {
        int i = base + (int)threadIdx.x;
        int v = (i < n) ? g_cnt[i] : 0;
        // inclusive warp scan
        int x = v;
        #pragma unroll
        for (int o = 1; o < 32; o <<= 1) {
            int y = __shfl_up_sync(0xffffffffu, x, o);
            if (lane >= o) x += y;
        }
        if (lane == 31) warpsums[warp] = x;
        __syncthreads();
        if (threadIdx.x < 32) {
            int s = warpsums[threadIdx.x];
            int xs = s;
            #pragma unroll
            for (int o = 1; o < 32; o <<= 1) {
                int y = __shfl_up_sync(0xffffffffu, xs, o);
                if ((int)threadIdx.x >= o) xs += y;
            }
            warpsums[threadIdx.x] = xs - s;  // exclusive warp offsets
        }
        __syncthreads();
        int excl = (x - v) + warpsums[warp] + carry_s;
        if (i < n) g_rowstart[i] = excl;
        __syncthreads();   // everyone done reading carry_s
        if (threadIdx.x == 1023) carry_s = excl + v;
        __syncthreads();
    }
    if (threadIdx.x == 0) g_rowstart[n] = carry_s;
}

// ---------------------------------------------------------------------------
// reorder edges into CSR-by-dst; fuse norm computation
// ---------------------------------------------------------------------------
__global__ void k_reorder(const int* __restrict__ src, const int* __restrict__ dst,
                          const float* __restrict__ ew, int e) {
    int i = blockIdx.x * blockDim.x + threadIdx.x;
    if (i < e) {
        int s = src[i];
        int d = dst[i];
        float nrm = g_dinv[s] * ew[i] * g_dinv[d];
        int p = g_rowstart[d] + atomicAdd(&g_cursor[d], 1);
        g_edges[p] = make_int2(s, __float_as_int(nrm));
    }
}

// ---------------------------------------------------------------------------
// GEMM: out[n,128] = in[n,128] @ W[128,128]
// W resident in smem (64KB). Block = 256 thr = 8 warps; 32 rows per iter.
// Warp computes 4 rows x 128 cols; lane holds 4 cols x 4 rows in regs.
// ---------------------------------------------------------------------------
__global__ void k_gemm(const float* __restrict__ in, const float* __restrict__ W,
                       float* __restrict__ out, int n) {
    extern __shared__ float smem[];
    float* Ws = smem;                 // [128][128]
    float* xs = smem + DIM * DIM;     // [32][128]

    for (int i = threadIdx.x; i < DIM * DIM4; i += blockDim.x)
        ((float4*)Ws)[i] = ((const float4*)W)[i];
    __syncthreads();

    const int warp = threadIdx.x >> 5;
    const int lane = threadIdx.x & 31;

    for (int row0 = blockIdx.x * 32; row0 < n; row0 += gridDim.x * 32) {
        const int nrows = min(32, n - row0);
        __syncthreads();  // xs reuse fence
        for (int i = threadIdx.x; i < nrows * DIM4; i += blockDim.x)
            ((float4*)xs)[i] = ((const float4*)(in + (size_t)row0 * DIM))[i];
        __syncthreads();

        const int r0 = warp * 4;
        float acc[4][4];
        #pragma unroll
        for (int r = 0; r < 4; r++)
            #pragma unroll
            for (int c = 0; c < 4; c++) acc[r][c] = 0.0f;

        #pragma unroll 4
        for (int k = 0; k < DIM; k++) {
            float4 wv = ((const float4*)(Ws + k * DIM))[lane];
            #pragma unroll
            for (int r = 0; r < 4; r++) {
                float xk = xs[(r0 + r) * DIM + k];
                acc[r][0] = fmaf(xk, wv.x, acc[r][0]);
                acc[r][1] = fmaf(xk, wv.y, acc[r][1]);
                acc[r][2] = fmaf(xk, wv.z, acc[r][2]);
                acc[r][3] = fmaf(xk, wv.w, acc[r][3]);
            }
        }

        #pragma unroll
        for (int r = 0; r < 4; r++) {
            int row = row0 + r0 + r;
            if (row < n)
                ((float4*)(out + (size_t)row * DIM))[lane] =
                    make_float4(acc[r][0], acc[r][1], acc[r][2], acc[r][3]);
        }
    }
}

// ---------------------------------------------------------------------------
// Gather-aggregate (no atomics): per dst node,
//   out[d] = relu( dinv[d]^2 * h[d] + sum_{e in CSR row d} norm_e * h[src_e] + b )
// One warp per node; lane owns 4 consecutive columns.
// ---------------------------------------------------------------------------
__global__ void k_agg(const float* __restrict__ h, const float* __restrict__ b,
                      float* __restrict__ out, int n) {
    int t = blockIdx.x * blockDim.x + threadIdx.x;
    int node = t >> 5;
    int lane = t & 31;
    if (node >= n) return;

    int beg = g_rowstart[node];
    int end = g_rowstart[node + 1];

    float di = g_dinv[node];
    float sl = di * di;
    float4 hv = ((const float4*)(h + (size_t)node * DIM))[lane];
    float4 acc = make_float4(hv.x * sl, hv.y * sl, hv.z * sl, hv.w * sl);

    for (int j0 = beg; j0 < end; j0 += 32) {
        int m = end - j0; if (m > 32) m = 32;
        int2 ed = make_int2(0, 0);
        if (lane < m) ed = g_edges[j0 + lane];

        int k = 0;
        for (; k + 4 <= m; k += 4) {
            int   s0 = __shfl_sync(0xffffffffu, ed.x, k + 0);
            float n0 = __int_as_float(__shfl_sync(0xffffffffu, ed.y, k + 0));
            int   s1 = __shfl_sync(0xffffffffu, ed.x, k + 1);
            float n1 = __int_as_float(__shfl_sync(0xffffffffu, ed.y, k + 1));
            int   s2 = __shfl_sync(0xffffffffu, ed.x, k + 2);
            float n2 = __int_as_float(__shfl_sync(0xffffffffu, ed.y, k + 2));
            int   s3 = __shfl_sync(0xffffffffu, ed.x, k + 3);
            float n3 = __int_as_float(__shfl_sync(0xffffffffu, ed.y, k + 3));
            float4 v0 = ((const float4*)(h + (size_t)s0 * DIM))[lane];
            float4 v1 = ((const float4*)(h + (size_t)s1 * DIM))[lane];
            float4 v2 = ((const float4*)(h + (size_t)s2 * DIM))[lane];
            float4 v3 = ((const float4*)(h + (size_t)s3 * DIM))[lane];
            acc.x = fmaf(n0, v0.x, acc.x); acc.y = fmaf(n0, v0.y, acc.y);
            acc.z = fmaf(n0, v0.z, acc.z); acc.w = fmaf(n0, v0.w, acc.w);
            acc.x = fmaf(n1, v1.x, acc.x); acc.y = fmaf(n1, v1.y, acc.y);
            acc.z = fmaf(n1, v1.z, acc.z); acc.w = fmaf(n1, v1.w, acc.w);
            acc.x = fmaf(n2, v2.x, acc.x); acc.y = fmaf(n2, v2.y, acc.y);
            acc.z = fmaf(n2, v2.z, acc.z); acc.w = fmaf(n2, v2.w, acc.w);
            acc.x = fmaf(n3, v3.x, acc.x); acc.y = fmaf(n3, v3.y, acc.y);
            acc.z = fmaf(n3, v3.z, acc.z); acc.w = fmaf(n3, v3.w, acc.w);
        }
        for (; k < m; k++) {
            int   s0 = __shfl_sync(0xffffffffu, ed.x, k);
            float n0 = __int_as_float(__shfl_sync(0xffffffffu, ed.y, k));
            float4 v0 = ((const float4*)(h + (size_t)s0 * DIM))[lane];
            acc.x = fmaf(n0, v0.x, acc.x); acc.y = fmaf(n0, v0.y, acc.y);
            acc.z = fmaf(n0, v0.z, acc.z); acc.w = fmaf(n0, v0.w, acc.w);
        }
    }

    float4 bv = ((const float4*)b)[lane];
    float4 o;
    o.x = fmaxf(acc.x + bv.x, 0.0f);
    o.y = fmaxf(acc.y + bv.y, 0.0f);
    o.z = fmaxf(acc.z + bv.z, 0.0f);
    o.w = fmaxf(acc.w + bv.w, 0.0f);
    ((float4*)(out + (size_t)node * DIM))[lane] = o;
}

// ---------------------------------------------------------------------------
// launch
// ---------------------------------------------------------------------------
extern "C" void kernel_launch(void* const* d_in, const int* in_sizes, int n_in,
                              void* d_out, int out_size) {
    const float* x   = (const float*)d_in[0];
    const int*   ei  = (const int*)d_in[1];      // [2, E]: src then dst
    const float* ew  = (const float*)d_in[2];
    const float* W1  = (const float*)d_in[3];
    const float* b1  = (const float*)d_in[4];
    const float* W2  = (const float*)d_in[5];
    const float* b2  = (const float*)d_in[6];
    float* out = (float*)d_out;

    const int n = in_sizes[0] / DIM;
    const int e = in_sizes[2];
    const int* src = ei;
    const int* dst = ei + e;

    const int T = 256;
    const int gN = (n + T - 1) / T;
    const int gE = (e + T - 1) / T;
    const int gW = ((n * 32) + T - 1) / T;   // warp-per-node grid

    static bool smem_set = false;  // host-side, idempotent
    const int GEMM_SMEM = (DIM * DIM + 32 * DIM) * sizeof(float);  // 80KB
    if (!smem_set) {
        cudaFuncSetAttribute(k_gemm, cudaFuncAttributeMaxDynamicSharedMemorySize, GEMM_SMEM);
        smem_set = true;
    }
    const int GEMM_GRID = 296;

    float* g_h_p;  cudaGetSymbolAddress((void**)&g_h_p, g_h);
    float* g_z_p;  cudaGetSymbolAddress((void**)&g_z_p, g_z);

    // --- CSR build + norm precompute (shared by both layers) ---
    k_init<<<gN, T>>>(n);
    k_count<<<gE, T>>>(dst, ew, e);
    k_dinv<<<gN, T>>>(n);
    k_scan<<<1, 1024>>>(n);
    k_reorder<<<gE, T>>>(src, dst, ew, e);

    // --- layer 1 ---
    k_gemm<<<GEMM_GRID, T, GEMM_SMEM>>>(x, W1, g_h_p, n);
    k_agg<<<gW, T>>>(g_h_p, b1, g_z_p, n);

    // --- layer 2 ---
    k_gemm<<<GEMM_GRID, T, GEMM_SMEM>>>(g_z_p, W2, g_h_p, n);
    k_agg<<<gW, T>>>(g_h_p, b2, out, n);
}

// round 3
// speedup vs baseline: 1.6497x; 1.2254x over previous
#include <cuda_runtime.h>
#include <cstdint>

#define N_NODES 50000
#define N_EDGES 800000
#define DIM 128
#define DIM4 (DIM/4)   // 32 float4 per row

// Scratch (allocation-free: __device__ globals)
__device__ float g_h[N_NODES * DIM];       // gemm output (reused both layers)
__device__ float g_z[N_NODES * DIM];       // layer-1 activations
__device__ float g_deg[N_NODES];
__device__ float g_dinv[N_NODES];
__device__ int   g_cnt[N_NODES];           // in-degree (edge count) per dst
__device__ int   g_cursor[N_NODES];        // placement cursor for reorder
__device__ int   g_rowstart[N_NODES + 1];  // CSR row offsets (by dst)
__device__ int   g_blocksums[128];         // partial sums for multi-block scan
__device__ int2  g_edges[N_EDGES];         // {src, __float_as_int(norm)} sorted by dst

// ---------------------------------------------------------------------------
// init: deg=1 (self loop), cnt=0, cursor=0
// ---------------------------------------------------------------------------
__global__ void k_init(int n) {
    int i = blockIdx.x * blockDim.x + threadIdx.x;
    if (i < n) { g_deg[i] = 1.0f; g_cnt[i] = 0; g_cursor[i] = 0; }
}

// histogram + weighted degree in one pass over edges
__global__ void k_count(const int* __restrict__ dst, const float* __restrict__ ew, int e) {
    int i = blockIdx.x * blockDim.x + threadIdx.x;
    if (i < e) {
        int d = dst[i];
        atomicAdd(&g_deg[d], ew[i]);
        atomicAdd(&g_cnt[d], 1);
    }
}

__global__ void k_dinv(int n) {
    int i = blockIdx.x * blockDim.x + threadIdx.x;
    if (i < n) g_dinv[i] = rsqrtf(g_deg[i]);   // deg >= 1 always (self loop)
}

// ---------------------------------------------------------------------------
// multi-block exclusive scan of g_cnt -> g_rowstart
// phase 1: per-block (1024 elems) exclusive scan + block total
// ---------------------------------------------------------------------------
__device__ __forceinline__ int warp_incl_scan(int x, int lane) {
    #pragma unroll
    for (int o = 1; o < 32; o <<= 1) {
        int y = __shfl_up_sync(0xffffffffu, x, o);
        if (lane >= o) x += y;
    }
    return x;
}

__global__ void k_scan1(int n) {
    __shared__ int warpsums[32];
    const int lane = threadIdx.x & 31;
    const int warp = threadIdx.x >> 5;
    int i = blockIdx.x * 1024 + threadIdx.x;
    int v = (i < n) ? g_cnt[i] : 0;
    int x = warp_incl_scan(v, lane);
    if (lane == 31) warpsums[warp] = x;
    __syncthreads();
    if (threadIdx.x < 32) {
        int s = warpsums[threadIdx.x];
        int xs = warp_incl_scan(s, threadIdx.x);
        warpsums[threadIdx.x] = xs - s;  // exclusive
    }
    __syncthreads();
    int excl = (x - v) + warpsums[warp];
    if (i < n) g_rowstart[i] = excl;
    if (threadIdx.x == 1023) g_blocksums[blockIdx.x] = excl + v;
}

// phase 2: single-warp scan of block sums (B <= 128); writes g_rowstart[n]=e
__global__ void k_scan2(int nblocks, int n, int e) {
    __shared__ int tmp[128];
    const int lane = threadIdx.x & 31;
    // two chunks of <=64? keep simple: serial-by-warp over 4 chunks of 32
    if (threadIdx.x < 128) tmp[threadIdx.x] = (threadIdx.x < nblocks) ? g_blocksums[threadIdx.x] : 0;
    __syncthreads();
    if (threadIdx.x < 32) {
        int carry = 0;
        for (int c = 0; c < 128; c += 32) {
            int v = tmp[c + lane];
            int x = warp_incl_scan(v, lane);
            tmp[c + lane] = (x - v) + carry;
            carry += __shfl_sync(0xffffffffu, x, 31);
        }
    }
    __syncthreads();
    if (threadIdx.x < 128 && threadIdx.x < nblocks) g_blocksums[threadIdx.x] = tmp[threadIdx.x];
    if (threadIdx.x == 0) g_rowstart[n] = e;
}

// phase 3: add block offsets
__global__ void k_scan3(int n) {
    int i = blockIdx.x * blockDim.x + threadIdx.x;
    if (i < n) g_rowstart[i] += g_blocksums[i >> 10];
}

// ---------------------------------------------------------------------------
// reorder edges into CSR-by-dst; fuse norm computation
// ---------------------------------------------------------------------------
__global__ void k_reorder(const int* __restrict__ src, const int* __restrict__ dst,
                          const float* __restrict__ ew, int e) {
    int i = blockIdx.x * blockDim.x + threadIdx.x;
    if (i < e) {
        int s = src[i];
        int d = dst[i];
        float nrm = g_dinv[s] * ew[i] * g_dinv[d];
        int p = g_rowstart[d] + atomicAdd(&g_cursor[d], 1);
        g_edges[p] = make_int2(s, __float_as_int(nrm));
    }
}

// ---------------------------------------------------------------------------
// GEMM: out[n,128] = in[n,128] @ W[128,128]
// W resident in smem (64KB). Block = 256 thr = 8 warps; 32 rows per iter.
// Warp computes 4 rows x 128 cols; lane holds 4 cols x 4 rows in regs.
// ---------------------------------------------------------------------------
__global__ void k_gemm(const float* __restrict__ in, const float* __restrict__ W,
                       float* __restrict__ out, int n) {
    extern __shared__ float smem[];
    float* Ws = smem;                 // [128][128]
    float* xs = smem + DIM * DIM;     // [32][128]

    for (int i = threadIdx.x; i < DIM * DIM4; i += blockDim.x)
        ((float4*)Ws)[i] = ((const float4*)W)[i];
    __syncthreads();

    const int warp = threadIdx.x >> 5;
    const int lane = threadIdx.x & 31;

    for (int row0 = blockIdx.x * 32; row0 < n; row0 += gridDim.x * 32) {
        const int nrows = min(32, n - row0);
        __syncthreads();  // xs reuse fence
        for (int i = threadIdx.x; i < nrows * DIM4; i += blockDim.x)
            ((float4*)xs)[i] = ((const float4*)(in + (size_t)row0 * DIM))[i];
        __syncthreads();

        const int r0 = warp * 4;
        float acc[4][4];
        #pragma unroll
        for (int r = 0; r < 4; r++)
            #pragma unroll
            for (int c = 0; c < 4; c++) acc[r][c] = 0.0f;

        #pragma unroll 4
        for (int k = 0; k < DIM; k++) {
            float4 wv = ((const float4*)(Ws + k * DIM))[lane];
            #pragma unroll
            for (int r = 0; r < 4; r++) {
                float xk = xs[(r0 + r) * DIM + k];
                acc[r][0] = fmaf(xk, wv.x, acc[r][0]);
                acc[r][1] = fmaf(xk, wv.y, acc[r][1]);
                acc[r][2] = fmaf(xk, wv.z, acc[r][2]);
                acc[r][3] = fmaf(xk, wv.w, acc[r][3]);
            }
        }

        #pragma unroll
        for (int r = 0; r < 4; r++) {
            int row = row0 + r0 + r;
            if (row < n)
                ((float4*)(out + (size_t)row * DIM))[lane] =
                    make_float4(acc[r][0], acc[r][1], acc[r][2], acc[r][3]);
        }
    }
}

// ---------------------------------------------------------------------------
// Gather-aggregate (no atomics): per dst node,
//   out[d] = relu( dinv[d]^2 * h[d] + sum_{e in CSR row d} norm_e * h[src_e] + b )
// One warp per node; lane owns 4 consecutive columns.
// ---------------------------------------------------------------------------
__global__ void k_agg(const float* __restrict__ h, const float* __restrict__ b,
                      float* __restrict__ out, int n) {
    int t = blockIdx.x * blockDim.x + threadIdx.x;
    int node = t >> 5;
    int lane = t & 31;
    if (node >= n) return;

    int beg = g_rowstart[node];
    int end = g_rowstart[node + 1];

    float di = g_dinv[node];
    float sl = di * di;
    float4 hv = ((const float4*)(h + (size_t)node * DIM))[lane];
    float4 acc = make_float4(hv.x * sl, hv.y * sl, hv.z * sl, hv.w * sl);

    for (int j0 = beg; j0 < end; j0 += 32) {
        int m = end - j0; if (m > 32) m = 32;
        int2 ed = make_int2(0, 0);
        if (lane < m) ed = g_edges[j0 + lane];

        int k = 0;
        for (; k + 4 <= m; k += 4) {
            int   s0 = __shfl_sync(0xffffffffu, ed.x, k + 0);
            float n0 = __int_as_float(__shfl_sync(0xffffffffu, ed.y, k + 0));
            int   s1 = __shfl_sync(0xffffffffu, ed.x, k + 1);
            float n1 = __int_as_float(__shfl_sync(0xffffffffu, ed.y, k + 1));
            int   s2 = __shfl_sync(0xffffffffu, ed.x, k + 2);
            float n2 = __int_as_float(__shfl_sync(0xffffffffu, ed.y, k + 2));
            int   s3 = __shfl_sync(0xffffffffu, ed.x, k + 3);
            float n3 = __int_as_float(__shfl_sync(0xffffffffu, ed.y, k + 3));
            float4 v0 = ((const float4*)(h + (size_t)s0 * DIM))[lane];
            float4 v1 = ((const float4*)(h + (size_t)s1 * DIM))[lane];
            float4 v2 = ((const float4*)(h + (size_t)s2 * DIM))[lane];
            float4 v3 = ((const float4*)(h + (size_t)s3 * DIM))[lane];
            acc.x = fmaf(n0, v0.x, acc.x); acc.y = fmaf(n0, v0.y, acc.y);
            acc.z = fmaf(n0, v0.z, acc.z); acc.w = fmaf(n0, v0.w, acc.w);
            acc.x = fmaf(n1, v1.x, acc.x); acc.y = fmaf(n1, v1.y, acc.y);
            acc.z = fmaf(n1, v1.z, acc.z); acc.w = fmaf(n1, v1.w, acc.w);
            acc.x = fmaf(n2, v2.x, acc.x); acc.y = fmaf(n2, v2.y, acc.y);
            acc.z = fmaf(n2, v2.z, acc.z); acc.w = fmaf(n2, v2.w, acc.w);
            acc.x = fmaf(n3, v3.x, acc.x); acc.y = fmaf(n3, v3.y, acc.y);
            acc.z = fmaf(n3, v3.z, acc.z); acc.w = fmaf(n3, v3.w, acc.w);
        }
        for (; k < m; k++) {
            int   s0 = __shfl_sync(0xffffffffu, ed.x, k);
            float n0 = __int_as_float(__shfl_sync(0xffffffffu, ed.y, k));
            float4 v0 = ((const float4*)(h + (size_t)s0 * DIM))[lane];
            acc.x = fmaf(n0, v0.x, acc.x); acc.y = fmaf(n0, v0.y, acc.y);
            acc.z = fmaf(n0, v0.z, acc.z); acc.w = fmaf(n0, v0.w, acc.w);
        }
    }

    float4 bv = ((const float4*)b)[lane];
    float4 o;
    o.x = fmaxf(acc.x + bv.x, 0.0f);
    o.y = fmaxf(acc.y + bv.y, 0.0f);
    o.z = fmaxf(acc.z + bv.z, 0.0f);
    o.w = fmaxf(acc.w + bv.w, 0.0f);
    ((float4*)(out + (size_t)node * DIM))[lane] = o;
}

// ---------------------------------------------------------------------------
// launch: fork-join — CSR build on side stream overlapped with GEMM-1
// ---------------------------------------------------------------------------
extern "C" void kernel_launch(void* const* d_in, const int* in_sizes, int n_in,
                              void* d_out, int out_size) {
    const float* x   = (const float*)d_in[0];
    const int*   ei  = (const int*)d_in[1];      // [2, E]: src then dst
    const float* ew  = (const float*)d_in[2];
    const float* W1  = (const float*)d_in[3];
    const float* b1  = (const float*)d_in[4];
    const float* W2  = (const float*)d_in[5];
    const float* b2  = (const float*)d_in[6];
    float* out = (float*)d_out;

    const int n = in_sizes[0] / DIM;
    const int e = in_sizes[2];
    const int* src = ei;
    const int* dst = ei + e;

    const int T = 256;
    const int gN = (n + T - 1) / T;
    const int gE = (e + T - 1) / T;
    const int gW = ((n * 32) + T - 1) / T;   // warp-per-node grid
    const int nScanBlk = (n + 1023) / 1024;

    static cudaStream_t s2 = nullptr;        // host-side objects, created once
    static cudaEvent_t ev_fork = nullptr, ev_join = nullptr;
    static bool smem_set = false;
    const int GEMM_SMEM = (DIM * DIM + 32 * DIM) * sizeof(float);  // 80KB
    if (!smem_set) {
        cudaFuncSetAttribute(k_gemm, cudaFuncAttributeMaxDynamicSharedMemorySize, GEMM_SMEM);
        cudaStreamCreateWithFlags(&s2, cudaStreamNonBlocking);
        cudaEventCreateWithFlags(&ev_fork, cudaEventDisableTiming);
        cudaEventCreateWithFlags(&ev_join, cudaEventDisableTiming);
        smem_set = true;
    }
    const int GEMM_GRID = 296;

    float* g_h_p;  cudaGetSymbolAddress((void**)&g_h_p, g_h);
    float* g_z_p;  cudaGetSymbolAddress((void**)&g_z_p, g_z);

    // fork: CSR build on s2, GEMM-1 on main (stream 0)
    cudaEventRecord(ev_fork, 0);
    cudaStreamWaitEvent(s2, ev_fork, 0);

    k_init<<<gN, T, 0, s2>>>(n);
    k_count<<<gE, T, 0, s2>>>(dst, ew, e);
    k_dinv<<<gN, T, 0, s2>>>(n);
    k_scan1<<<nScanBlk, 1024, 0, s2>>>(n);
    k_scan2<<<1, 128, 0, s2>>>(nScanBlk, n, e);
    k_scan3<<<gN, T, 0, s2>>>(n);
    k_reorder<<<gE, T, 0, s2>>>(src, dst, ew, e);
    cudaEventRecord(ev_join, s2);

    k_gemm<<<GEMM_GRID, T, GEMM_SMEM>>>(x, W1, g_h_p, n);

    // join before aggregation needs the CSR
    cudaStreamWaitEvent(0, ev_join, 0);

    k_agg<<<gW, T>>>(g_h_p, b1, g_z_p, n);
    k_gemm<<<GEMM_GRID, T, GEMM_SMEM>>>(g_z_p, W2, g_h_p, n);
    k_agg<<<gW, T>>>(g_h_p, b2, out, n);
}

// round 4
// speedup vs baseline: 1.9295x; 1.1696x over previous
#include <cuda_runtime.h>
#include <cstdint>

#define N_NODES 50000
#define N_EDGES 800000
#define DIM 128
#define DIM4 (DIM/4)

// Scratch (allocation-free: __device__ globals)
__device__ float g_h[N_NODES * DIM];
__device__ float g_z[N_NODES * DIM];
__device__ float g_deg[N_NODES];
__device__ float g_dinv[N_NODES];
__device__ int   g_cnt[N_NODES];
__device__ int   g_cursor[N_NODES];
__device__ int   g_rowstart[N_NODES + 1];
__device__ int   g_blocksums[128];
__device__ int2  g_edges[N_EDGES];

// ---------------------------------------------------------------------------
__global__ void k_init(int n) {
    int i = blockIdx.x * blockDim.x + threadIdx.x;
    if (i < n) { g_deg[i] = 1.0f; g_cnt[i] = 0; g_cursor[i] = 0; }
}

__global__ void k_count(const int* __restrict__ dst, const float* __restrict__ ew, int e) {
    int i = blockIdx.x * blockDim.x + threadIdx.x;
    if (i < e) {
        int d = dst[i];
        atomicAdd(&g_deg[d], ew[i]);
        atomicAdd(&g_cnt[d], 1);
    }
}

__global__ void k_dinv(int n) {
    int i = blockIdx.x * blockDim.x + threadIdx.x;
    if (i < n) g_dinv[i] = rsqrtf(g_deg[i]);
}

// ---------------------------------------------------------------------------
__device__ __forceinline__ int warp_incl_scan(int x, int lane) {
    #pragma unroll
    for (int o = 1; o < 32; o <<= 1) {
        int y = __shfl_up_sync(0xffffffffu, x, o);
        if (lane >= o) x += y;
    }
    return x;
}

__global__ void k_scan1(int n) {
    __shared__ int warpsums[32];
    const int lane = threadIdx.x & 31;
    const int warp = threadIdx.x >> 5;
    int i = blockIdx.x * 1024 + threadIdx.x;
    int v = (i < n) ? g_cnt[i] : 0;
    int x = warp_incl_scan(v, lane);
    if (lane == 31) warpsums[warp] = x;
    __syncthreads();
    if (threadIdx.x < 32) {
        int s = warpsums[threadIdx.x];
        int xs = warp_incl_scan(s, threadIdx.x);
        warpsums[threadIdx.x] = xs - s;
    }
    __syncthreads();
    int excl = (x - v) + warpsums[warp];
    if (i < n) g_rowstart[i] = excl;
    if (threadIdx.x == 1023) g_blocksums[blockIdx.x] = excl + v;
}

__global__ void k_scan2(int nblocks, int n, int e) {
    __shared__ int tmp[128];
    const int lane = threadIdx.x & 31;
    if (threadIdx.x < 128) tmp[threadIdx.x] = (threadIdx.x < nblocks) ? g_blocksums[threadIdx.x] : 0;
    __syncthreads();
    if (threadIdx.x < 32) {
        int carry = 0;
        for (int c = 0; c < 128; c += 32) {
            int v = tmp[c + lane];
            int x = warp_incl_scan(v, lane);
            tmp[c + lane] = (x - v) + carry;
            carry += __shfl_sync(0xffffffffu, x, 31);
        }
    }
    __syncthreads();
    if (threadIdx.x < 128 && threadIdx.x < nblocks) g_blocksums[threadIdx.x] = tmp[threadIdx.x];
    if (threadIdx.x == 0) g_rowstart[n] = e;
}

__global__ void k_scan3(int n) {
    int i = blockIdx.x * blockDim.x + threadIdx.x;
    if (i < n) g_rowstart[i] += g_blocksums[i >> 10];
}

__global__ void k_reorder(const int* __restrict__ src, const int* __restrict__ dst,
                          const float* __restrict__ ew, int e) {
    int i = blockIdx.x * blockDim.x + threadIdx.x;
    if (i < e) {
        int s = src[i];
        int d = dst[i];
        float nrm = g_dinv[s] * ew[i] * g_dinv[d];
        int p = g_rowstart[d] + atomicAdd(&g_cursor[d], 1);
        g_edges[p] = make_int2(s, __float_as_int(nrm));
    }
}

// ---------------------------------------------------------------------------
// tf32 tensor-core GEMM: out[n,128] = in[n,128] @ W[128,128]
// Block = 128 threads (4 warps, 2x2), block tile 64 rows x 128 cols.
// Warp tile 32x64 = 2 m-tiles x 8 n-tiles of m16n8k8 mma. K = 128 (16 steps).
// A smem stride 132, W smem stride 136 -> conflict-free fragment loads.
// Explicit cvt.rna.tf32.f32 on staging (unbiased rounding; truncation would
// introduce a systematic ~1e-3 relative bias).
// ---------------------------------------------------------------------------
#define AS 132
#define WS 136

__device__ __forceinline__ uint32_t f2tf32(float v) {
    uint32_t o;
    asm("cvt.rna.tf32.f32 %0, %1;" : "=r"(o) : "f"(v));
    return o;
}

__device__ __forceinline__ void mma_tf32(float* c, const uint32_t* a,
                                         uint32_t b0, uint32_t b1) {
    asm volatile(
        "mma.sync.aligned.m16n8k8.row.col.f32.tf32.tf32.f32 "
        "{%0,%1,%2,%3}, {%4,%5,%6,%7}, {%8,%9}, {%0,%1,%2,%3};"
        : "+f"(c[0]), "+f"(c[1]), "+f"(c[2]), "+f"(c[3])
        : "r"(a[0]), "r"(a[1]), "r"(a[2]), "r"(a[3]), "r"(b0), "r"(b1));
}

__global__ void __launch_bounds__(128, 2)
k_gemm(const float* __restrict__ in, const float* __restrict__ W,
       float* __restrict__ out, int n) {
    extern __shared__ uint32_t smem[];
    uint32_t* Ws = smem;               // [128][WS]
    uint32_t* As = smem + DIM * WS;    // [64][AS]

    const int lane = threadIdx.x & 31;
    const int warp = threadIdx.x >> 5;
    const int warp_m = (warp & 1) * 32;
    const int warp_n = (warp >> 1) * 64;

    // Stage W -> smem (tf32, padded stride). 128x32 float4 = 4096 float4.
    for (int i = threadIdx.x; i < DIM * DIM4; i += blockDim.x) {
        int k = i >> 5, c4 = (i & 31) << 2;
        float4 v = ((const float4*)W)[i];
        uint32_t* p = Ws + k * WS + c4;
        p[0] = f2tf32(v.x); p[1] = f2tf32(v.y); p[2] = f2tf32(v.z); p[3] = f2tf32(v.w);
    }
    __syncthreads();

    for (int row0 = blockIdx.x * 64; row0 < n; row0 += gridDim.x * 64) {
        __syncthreads();  // As reuse fence
        // Stage A tile (64 rows) -> smem. 64x32 float4 = 2048.
        for (int i = threadIdx.x; i < 64 * DIM4; i += blockDim.x) {
            int r = i >> 5, c4 = (i & 31) << 2;
            if (row0 + r < n) {
                float4 v = ((const float4*)(in + (size_t)(row0 + r) * DIM))[i & 31];
                uint32_t* p = As + r * AS + c4;
                p[0] = f2tf32(v.x); p[1] = f2tf32(v.y); p[2] = f2tf32(v.z); p[3] = f2tf32(v.w);
            }
        }
        __syncthreads();

        float acc[2][8][4];
        #pragma unroll
        for (int mt = 0; mt < 2; mt++)
            #pragma unroll
            for (int nt = 0; nt < 8; nt++)
                #pragma unroll
                for (int q = 0; q < 4; q++) acc[mt][nt][q] = 0.0f;

        const int ar = lane >> 2;
        const int akc = lane & 3;
        #pragma unroll
        for (int ks = 0; ks < 16; ks++) {
            const int k0 = ks * 8;
            uint32_t a[2][4];
            #pragma unroll
            for (int mt = 0; mt < 2; mt++) {
                int r = warp_m + mt * 16 + ar;
                a[mt][0] = As[r * AS + k0 + akc];
                a[mt][1] = As[(r + 8) * AS + k0 + akc];
                a[mt][2] = As[r * AS + k0 + akc + 4];
                a[mt][3] = As[(r + 8) * AS + k0 + akc + 4];
            }
            #pragma unroll
            for (int nt = 0; nt < 8; nt++) {
                int bn = warp_n + nt * 8 + (lane >> 2);
                int bk = k0 + (lane & 3);
                uint32_t b0 = Ws[bk * WS + bn];
                uint32_t b1 = Ws[(bk + 4) * WS + bn];
                mma_tf32(acc[0][nt], a[0], b0, b1);
                mma_tf32(acc[1][nt], a[1], b0, b1);
            }
        }

        // Store: c0,c1 -> (row, 2*(lane%4)); c2,c3 -> (row+8, same cols)
        #pragma unroll
        for (int mt = 0; mt < 2; mt++) {
            int rbase = row0 + warp_m + mt * 16 + (lane >> 2);
            #pragma unroll
            for (int nt = 0; nt < 8; nt++) {
                int col = warp_n + nt * 8 + 2 * (lane & 3);
                if (rbase < n)
                    *(float2*)(out + (size_t)rbase * DIM + col) =
                        make_float2(acc[mt][nt][0], acc[mt][nt][1]);
                if (rbase + 8 < n)
                    *(float2*)(out + (size_t)(rbase + 8) * DIM + col) =
                        make_float2(acc[mt][nt][2], acc[mt][nt][3]);
            }
        }
    }
}

// ---------------------------------------------------------------------------
// Gather-aggregate (no atomics): per dst node,
//   out[d] = relu( dinv[d]^2 * h[d] + sum_{e in CSR row d} norm_e * h[src_e] + b )
// ---------------------------------------------------------------------------
__global__ void k_agg(const float* __restrict__ h, const float* __restrict__ b,
                      float* __restrict__ out, int n) {
    int t = blockIdx.x * blockDim.x + threadIdx.x;
    int node = t >> 5;
    int lane = t & 31;
    if (node >= n) return;

    int beg = g_rowstart[node];
    int end = g_rowstart[node + 1];

    float di = g_dinv[node];
    float sl = di * di;
    float4 hv = ((const float4*)(h + (size_t)node * DIM))[lane];
    float4 acc = make_float4(hv.x * sl, hv.y * sl, hv.z * sl, hv.w * sl);

    for (int j0 = beg; j0 < end; j0 += 32) {
        int m = end - j0; if (m > 32) m = 32;
        int2 ed = make_int2(0, 0);
        if (lane < m) ed = g_edges[j0 + lane];

        int k = 0;
        for (; k + 4 <= m; k += 4) {
            int   s0 = __shfl_sync(0xffffffffu, ed.x, k + 0);
            float n0 = __int_as_float(__shfl_sync(0xffffffffu, ed.y, k + 0));
            int   s1 = __shfl_sync(0xffffffffu, ed.x, k + 1);
            float n1 = __int_as_float(__shfl_sync(0xffffffffu, ed.y, k + 1));
            int   s2 = __shfl_sync(0xffffffffu, ed.x, k + 2);
            float n2 = __int_as_float(__shfl_sync(0xffffffffu, ed.y, k + 2));
            int   s3 = __shfl_sync(0xffffffffu, ed.x, k + 3);
            float n3 = __int_as_float(__shfl_sync(0xffffffffu, ed.y, k + 3));
            float4 v0 = ((const float4*)(h + (size_t)s0 * DIM))[lane];
            float4 v1 = ((const float4*)(h + (size_t)s1 * DIM))[lane];
            float4 v2 = ((const float4*)(h + (size_t)s2 * DIM))[lane];
            float4 v3 = ((const float4*)(h + (size_t)s3 * DIM))[lane];
            acc.x = fmaf(n0, v0.x, acc.x); acc.y = fmaf(n0, v0.y, acc.y);
            acc.z = fmaf(n0, v0.z, acc.z); acc.w = fmaf(n0, v0.w, acc.w);
            acc.x = fmaf(n1, v1.x, acc.x); acc.y = fmaf(n1, v1.y, acc.y);
            acc.z = fmaf(n1, v1.z, acc.z); acc.w = fmaf(n1, v1.w, acc.w);
            acc.x = fmaf(n2, v2.x, acc.x); acc.y = fmaf(n2, v2.y, acc.y);
            acc.z = fmaf(n2, v2.z, acc.z); acc.w = fmaf(n2, v2.w, acc.w);
            acc.x = fmaf(n3, v3.x, acc.x); acc.y = fmaf(n3, v3.y, acc.y);
            acc.z = fmaf(n3, v3.z, acc.z); acc.w = fmaf(n3, v3.w, acc.w);
        }
        for (; k < m; k++) {
            int   s0 = __shfl_sync(0xffffffffu, ed.x, k);
            float n0 = __int_as_float(__shfl_sync(0xffffffffu, ed.y, k));
            float4 v0 = ((const float4*)(h + (size_t)s0 * DIM))[lane];
            acc.x = fmaf(n0, v0.x, acc.x); acc.y = fmaf(n0, v0.y, acc.y);
            acc.z = fmaf(n0, v0.z, acc.z); acc.w = fmaf(n0, v0.w, acc.w);
        }
    }

    float4 bv = ((const float4*)b)[lane];
    float4 o;
    o.x = fmaxf(acc.x + bv.x, 0.0f);
    o.y = fmaxf(acc.y + bv.y, 0.0f);
    o.z = fmaxf(acc.z + bv.z, 0.0f);
    o.w = fmaxf(acc.w + bv.w, 0.0f);
    ((float4*)(out + (size_t)node * DIM))[lane] = o;
}

// ---------------------------------------------------------------------------
extern "C" void kernel_launch(void* const* d_in, const int* in_sizes, int n_in,
                              void* d_out, int out_size) {
    const float* x   = (const float*)d_in[0];
    const int*   ei  = (const int*)d_in[1];
    const float* ew  = (const float*)d_in[2];
    const float* W1  = (const float*)d_in[3];
    const float* b1  = (const float*)d_in[4];
    const float* W2  = (const float*)d_in[5];
    const float* b2  = (const float*)d_in[6];
    float* out = (float*)d_out;

    const int n = in_sizes[0] / DIM;
    const int e = in_sizes[2];
    const int* src = ei;
    const int* dst = ei + e;

    const int T = 256;
    const int gN = (n + T - 1) / T;
    const int gE = (e + T - 1) / T;
    const int gW = ((n * 32) + T - 1) / T;
    const int nScanBlk = (n + 1023) / 1024;

    static cudaStream_t s2 = nullptr;
    static cudaEvent_t ev_fork = nullptr, ev_join = nullptr;
    static bool init_done = false;
    const int GEMM_SMEM = (DIM * WS + 64 * AS) * sizeof(uint32_t);  // ~103.4KB
    if (!init_done) {
        cudaFuncSetAttribute(k_gemm, cudaFuncAttributeMaxDynamicSharedMemorySize, GEMM_SMEM);
        cudaStreamCreateWithFlags(&s2, cudaStreamNonBlocking);
        cudaEventCreateWithFlags(&ev_fork, cudaEventDisableTiming);
        cudaEventCreateWithFlags(&ev_join, cudaEventDisableTiming);
        init_done = true;
    }
    const int GEMM_GRID = 296;

    float* g_h_p;  cudaGetSymbolAddress((void**)&g_h_p, g_h);
    float* g_z_p;  cudaGetSymbolAddress((void**)&g_z_p, g_z);

    // fork: CSR build on s2, GEMM-1 on main
    cudaEventRecord(ev_fork, 0);
    cudaStreamWaitEvent(s2, ev_fork, 0);

    k_init<<<gN, T, 0, s2>>>(n);
    k_count<<<gE, T, 0, s2>>>(dst, ew, e);
    k_dinv<<<gN, T, 0, s2>>>(n);
    k_scan1<<<nScanBlk, 1024, 0, s2>>>(n);
    k_scan2<<<1, 128, 0, s2>>>(nScanBlk, n, e);
    k_scan3<<<gN, T, 0, s2>>>(n);
    k_reorder<<<gE, T, 0, s2>>>(src, dst, ew, e);
    cudaEventRecord(ev_join, s2);

    k_gemm<<<GEMM_GRID, 128, GEMM_SMEM>>>(x, W1, g_h_p, n);

    cudaStreamWaitEvent(0, ev_join, 0);

    k_agg<<<gW, T>>>(g_h_p, b1, g_z_p, n);
    k_gemm<<<GEMM_GRID, 128, GEMM_SMEM>>>(g_z_p, W2, g_h_p, n);
    k_agg<<<gW, T>>>(g_h_p, b2, out, n);
}

// round 5
// speedup vs baseline: 2.2176x; 1.1493x over previous
#include <cuda_runtime.h>
#include <cstdint>

#define N_NODES 50000
#define N_EDGES 800000
#define DIM 128
#define DIM4 32
#define AS 132      // A smem stride (floats)
#define WS 136      // W smem stride (floats)
#define TM 128      // gemm tile rows

// Scratch (allocation-free: __device__ globals)
__device__ float g_h[N_NODES * DIM];
__device__ float g_z[N_NODES * DIM];
__device__ float g_deg[N_NODES];
__device__ float g_dinv[N_NODES];
__device__ int   g_cnt[N_NODES];
__device__ int   g_cursor[N_NODES];
__device__ int   g_rowstart[N_NODES + 1];
__device__ int   g_blocksums[128];
__device__ int2  g_edges[N_EDGES];

// ---------------------------------------------------------------------------
__global__ void k_init(int n) {
    int i = blockIdx.x * blockDim.x + threadIdx.x;
    if (i < n) { g_deg[i] = 1.0f; g_cnt[i] = 0; g_cursor[i] = 0; }
}

__global__ void k_count(const int* __restrict__ dst, const float* __restrict__ ew, int e) {
    int i = blockIdx.x * blockDim.x + threadIdx.x;
    if (i < e) {
        int d = dst[i];
        atomicAdd(&g_deg[d], ew[i]);
        atomicAdd(&g_cnt[d], 1);
    }
}

// ---------------------------------------------------------------------------
__device__ __forceinline__ int warp_incl_scan(int x, int lane) {
    #pragma unroll
    for (int o = 1; o < 32; o <<= 1) {
        int y = __shfl_up_sync(0xffffffffu, x, o);
        if (lane >= o) x += y;
    }
    return x;
}

// scan phase 1 (+ fused dinv: deg is final once k_count is done)
__global__ void k_scan1(int n) {
    __shared__ int warpsums[32];
    const int lane = threadIdx.x & 31;
    const int warp = threadIdx.x >> 5;
    int i = blockIdx.x * 1024 + threadIdx.x;
    if (i < n) g_dinv[i] = rsqrtf(g_deg[i]);
    int v = (i < n) ? g_cnt[i] : 0;
    int x = warp_incl_scan(v, lane);
    if (lane == 31) warpsums[warp] = x;
    __syncthreads();
    if (threadIdx.x < 32) {
        int s = warpsums[threadIdx.x];
        int xs = warp_incl_scan(s, threadIdx.x);
        warpsums[threadIdx.x] = xs - s;
    }
    __syncthreads();
    int excl = (x - v) + warpsums[warp];
    if (i < n) g_rowstart[i] = excl;
    if (threadIdx.x == 1023) g_blocksums[blockIdx.x] = excl + v;
}

__global__ void k_scan2(int nblocks, int n, int e) {
    __shared__ int tmp[128];
    const int lane = threadIdx.x & 31;
    if (threadIdx.x < 128) tmp[threadIdx.x] = (threadIdx.x < nblocks) ? g_blocksums[threadIdx.x] : 0;
    __syncthreads();
    if (threadIdx.x < 32) {
        int carry = 0;
        for (int c = 0; c < 128; c += 32) {
            int v = tmp[c + lane];
            int x = warp_incl_scan(v, lane);
            tmp[c + lane] = (x - v) + carry;
            carry += __shfl_sync(0xffffffffu, x, 31);
        }
    }
    __syncthreads();
    if (threadIdx.x < 128 && threadIdx.x < nblocks) g_blocksums[threadIdx.x] = tmp[threadIdx.x];
    if (threadIdx.x == 0) g_rowstart[n] = e;
}

__global__ void k_scan3(int n) {
    int i = blockIdx.x * blockDim.x + threadIdx.x;
    if (i < n) g_rowstart[i] += g_blocksums[i >> 10];
}

__global__ void k_reorder(const int* __restrict__ src, const int* __restrict__ dst,
                          const float* __restrict__ ew, int e) {
    int i = blockIdx.x * blockDim.x + threadIdx.x;
    if (i < e) {
        int s = src[i];
        int d = dst[i];
        float nrm = g_dinv[s] * ew[i] * g_dinv[d];
        int p = g_rowstart[d] + atomicAdd(&g_cursor[d], 1);
        g_edges[p] = make_int2(s, __float_as_int(nrm));
    }
}

// ---------------------------------------------------------------------------
// tf32 tensor GEMM v2: persistent, cp.async double-buffered A, 128x128 tile.
// 256 thr = 8 warps (4x2): warp tile 32x64. Conflict-free padded strides.
// W converted to tf32 (cvt.rna, unbiased) once; A converted at fragment load.
// ---------------------------------------------------------------------------
__device__ __forceinline__ uint32_t f2tf32(float v) {
    uint32_t o;
    asm("cvt.rna.tf32.f32 %0, %1;" : "=r"(o) : "f"(v));
    return o;
}

__device__ __forceinline__ void mma_tf32(float* c, const uint32_t* a,
                                         uint32_t b0, uint32_t b1) {
    asm volatile(
        "mma.sync.aligned.m16n8k8.row.col.f32.tf32.tf32.f32 "
        "{%0,%1,%2,%3}, {%4,%5,%6,%7}, {%8,%9}, {%0,%1,%2,%3};"
        : "+f"(c[0]), "+f"(c[1]), "+f"(c[2]), "+f"(c[3])
        : "r"(a[0]), "r"(a[1]), "r"(a[2]), "r"(a[3]), "r"(b0), "r"(b1));
}

__device__ __forceinline__ void load_tileA(float* dst, const float* __restrict__ in,
                                           int t, int n, int tid) {
    int row0 = t * TM;
    #pragma unroll 4
    for (int i = tid; i < TM * 32; i += 256) {
        int r = i >> 5, c = (i & 31) << 2;
        float* d = dst + r * AS + c;
        if (row0 + r < n) {
            uint32_t s = (uint32_t)__cvta_generic_to_shared(d);
            asm volatile("cp.async.cg.shared.global [%0], [%1], 16;"
                         :: "r"(s), "l"(in + (size_t)(row0 + r) * DIM + c));
        } else {
            *(float4*)d = make_float4(0.f, 0.f, 0.f, 0.f);
        }
    }
}

__global__ void __launch_bounds__(256, 1)
k_gemm(const float* __restrict__ in, const float* __restrict__ W,
       float* __restrict__ out, int n) {
    extern __shared__ uint32_t smem[];
    uint32_t* Ws = smem;                                  // [128][WS] tf32
    float* As0 = (float*)(smem + DIM * WS);               // [128][AS] fp32
    float* As1 = As0 + TM * AS;

    const int tid  = threadIdx.x;
    const int lane = tid & 31;
    const int warp = tid >> 5;
    const int warp_m = (warp & 3) * 32;
    const int warp_n = (warp >> 2) * 64;
    const int ntiles = (n + TM - 1) / TM;

    // stage W -> tf32 smem
    for (int i = tid; i < DIM * DIM4; i += 256) {
        int k = i >> 5, c4 = (i & 31) << 2;
        float4 v = ((const float4*)W)[i];
        uint32_t* p = Ws + k * WS + c4;
        p[0] = f2tf32(v.x); p[1] = f2tf32(v.y); p[2] = f2tf32(v.z); p[3] = f2tf32(v.w);
    }

    int t = blockIdx.x;
    if (t < ntiles) {
        load_tileA(As0, in, t, n, tid);
        asm volatile("cp.async.commit_group;");
    }

    int buf = 0;
    const int ar  = lane >> 2;
    const int akc = lane & 3;

    for (; t < ntiles; t += gridDim.x) {
        int tn = t + gridDim.x;
        if (tn < ntiles) {
            load_tileA(buf ? As0 : As1, in, tn, n, tid);
            asm volatile("cp.async.commit_group;");
            asm volatile("cp.async.wait_group 1;");
        } else {
            asm volatile("cp.async.wait_group 0;");
        }
        __syncthreads();   // also covers W staging on first iteration

        const float* A = buf ? As1 : As0;
        float acc[2][8][4];
        #pragma unroll
        for (int mt = 0; mt < 2; mt++)
            #pragma unroll
            for (int nt = 0; nt < 8; nt++)
                #pragma unroll
                for (int q = 0; q < 4; q++) acc[mt][nt][q] = 0.0f;

        #pragma unroll
        for (int ks = 0; ks < 16; ks++) {
            const int k0 = ks * 8;
            uint32_t a[2][4];
            #pragma unroll
            for (int mt = 0; mt < 2; mt++) {
                int r = warp_m + mt * 16 + ar;
                a[mt][0] = f2tf32(A[r * AS + k0 + akc]);
                a[mt][1] = f2tf32(A[(r + 8) * AS + k0 + akc]);
                a[mt][2] = f2tf32(A[r * AS + k0 + akc + 4]);
                a[mt][3] = f2tf32(A[(r + 8) * AS + k0 + akc + 4]);
            }
            #pragma unroll
            for (int nt = 0; nt < 8; nt++) {
                int bn = warp_n + nt * 8 + (lane >> 2);
                int bk = k0 + (lane & 3);
                uint32_t b0 = Ws[bk * WS + bn];
                uint32_t b1 = Ws[(bk + 4) * WS + bn];
                mma_tf32(acc[0][nt], a[0], b0, b1);
                mma_tf32(acc[1][nt], a[1], b0, b1);
            }
        }

        int row0 = t * TM;
        #pragma unroll
        for (int mt = 0; mt < 2; mt++) {
            int rbase = row0 + warp_m + mt * 16 + (lane >> 2);
            #pragma unroll
            for (int nt = 0; nt < 8; nt++) {
                int col = warp_n + nt * 8 + 2 * (lane & 3);
                if (rbase < n)
                    *(float2*)(out + (size_t)rbase * DIM + col) =
                        make_float2(acc[mt][nt][0], acc[mt][nt][1]);
                if (rbase + 8 < n)
                    *(float2*)(out + (size_t)(rbase + 8) * DIM + col) =
                        make_float2(acc[mt][nt][2], acc[mt][nt][3]);
            }
        }
        __syncthreads();   // tile buffer free for next prefetch
        buf ^= 1;
    }
}

// ---------------------------------------------------------------------------
// Gather-aggregate (no atomics)
// ---------------------------------------------------------------------------
__global__ void k_agg(const float* __restrict__ h, const float* __restrict__ b,
                      float* __restrict__ out, int n) {
    int t = blockIdx.x * blockDim.x + threadIdx.x;
    int node = t >> 5;
    int lane = t & 31;
    if (node >= n) return;

    int beg = g_rowstart[node];
    int end = g_rowstart[node + 1];

    float di = g_dinv[node];
    float sl = di * di;
    float4 hv = ((const float4*)(h + (size_t)node * DIM))[lane];
    float4 acc = make_float4(hv.x * sl, hv.y * sl, hv.z * sl, hv.w * sl);

    for (int j0 = beg; j0 < end; j0 += 32) {
        int m = end - j0; if (m > 32) m = 32;
        int2 ed = make_int2(0, 0);
        if (lane < m) ed = g_edges[j0 + lane];

        int k = 0;
        for (; k + 4 <= m; k += 4) {
            int   s0 = __shfl_sync(0xffffffffu, ed.x, k + 0);
            float n0 = __int_as_float(__shfl_sync(0xffffffffu, ed.y, k + 0));
            int   s1 = __shfl_sync(0xffffffffu, ed.x, k + 1);
            float n1 = __int_as_float(__shfl_sync(0xffffffffu, ed.y, k + 1));
            int   s2 = __shfl_sync(0xffffffffu, ed.x, k + 2);
            float n2 = __int_as_float(__shfl_sync(0xffffffffu, ed.y, k + 2));
            int   s3 = __shfl_sync(0xffffffffu, ed.x, k + 3);
            float n3 = __int_as_float(__shfl_sync(0xffffffffu, ed.y, k + 3));
            float4 v0 = ((const float4*)(h + (size_t)s0 * DIM))[lane];
            float4 v1 = ((const float4*)(h + (size_t)s1 * DIM))[lane];
            float4 v2 = ((const float4*)(h + (size_t)s2 * DIM))[lane];
            float4 v3 = ((const float4*)(h + (size_t)s3 * DIM))[lane];
            acc.x = fmaf(n0, v0.x, acc.x); acc.y = fmaf(n0, v0.y, acc.y);
            acc.z = fmaf(n0, v0.z, acc.z); acc.w = fmaf(n0, v0.w, acc.w);
            acc.x = fmaf(n1, v1.x, acc.x); acc.y = fmaf(n1, v1.y, acc.y);
            acc.z = fmaf(n1, v1.z, acc.z); acc.w = fmaf(n1, v1.w, acc.w);
            acc.x = fmaf(n2, v2.x, acc.x); acc.y = fmaf(n2, v2.y, acc.y);
            acc.z = fmaf(n2, v2.z, acc.z); acc.w = fmaf(n2, v2.w, acc.w);
            acc.x = fmaf(n3, v3.x, acc.x); acc.y = fmaf(n3, v3.y, acc.y);
            acc.z = fmaf(n3, v3.z, acc.z); acc.w = fmaf(n3, v3.w, acc.w);
        }
        for (; k < m; k++) {
            int   s0 = __shfl_sync(0xffffffffu, ed.x, k);
            float n0 = __int_as_float(__shfl_sync(0xffffffffu, ed.y, k));
            float4 v0 = ((const float4*)(h + (size_t)s0 * DIM))[lane];
            acc.x = fmaf(n0, v0.x, acc.x); acc.y = fmaf(n0, v0.y, acc.y);
            acc.z = fmaf(n0, v0.z, acc.z); acc.w = fmaf(n0, v0.w, acc.w);
        }
    }

    float4 bv = ((const float4*)b)[lane];
    float4 o;
    o.x = fmaxf(acc.x + bv.x, 0.0f);
    o.y = fmaxf(acc.y + bv.y, 0.0f);
    o.z = fmaxf(acc.z + bv.z, 0.0f);
    o.w = fmaxf(acc.w + bv.w, 0.0f);
    ((float4*)(out + (size_t)node * DIM))[lane] = o;
}

// ---------------------------------------------------------------------------
extern "C" void kernel_launch(void* const* d_in, const int* in_sizes, int n_in,
                              void* d_out, int out_size) {
    const float* x   = (const float*)d_in[0];
    const int*   ei  = (const int*)d_in[1];
    const float* ew  = (const float*)d_in[2];
    const float* W1  = (const float*)d_in[3];
    const float* b1  = (const float*)d_in[4];
    const float* W2  = (const float*)d_in[5];
    const float* b2  = (const float*)d_in[6];
    float* out = (float*)d_out;

    const int n = in_sizes[0] / DIM;
    const int e = in_sizes[2];
    const int* src = ei;
    const int* dst = ei + e;

    const int T = 256;
    const int gN = (n + T - 1) / T;
    const int gE = (e + T - 1) / T;
    const int gW = ((n * 32) + T - 1) / T;
    const int nScanBlk = (n + 1023) / 1024;

    static cudaStream_t s2 = nullptr;
    static cudaEvent_t ev_fork = nullptr, ev_join = nullptr;
    static bool init_done = false;
    const int GEMM_SMEM = (DIM * WS + 2 * TM * AS) * sizeof(uint32_t);  // 200KB
    if (!init_done) {
        cudaFuncSetAttribute(k_gemm, cudaFuncAttributeMaxDynamicSharedMemorySize, GEMM_SMEM);
        cudaStreamCreateWithFlags(&s2, cudaStreamNonBlocking);
        cudaEventCreateWithFlags(&ev_fork, cudaEventDisableTiming);
        cudaEventCreateWithFlags(&ev_join, cudaEventDisableTiming);
        init_done = true;
    }
    const int GEMM_GRID = 148;

    float* g_h_p;  cudaGetSymbolAddress((void**)&g_h_p, g_h);
    float* g_z_p;  cudaGetSymbolAddress((void**)&g_z_p, g_z);

    // fork: CSR build on s2, GEMM-1 on main.
    // gemm1 is submitted as the 4th kernel so the profiler's fixed capture
    // ordinal lands on it next time.
    cudaEventRecord(ev_fork, 0);
    cudaStreamWaitEvent(s2, ev_fork, 0);

    k_init<<<gN, T, 0, s2>>>(n);                    // 0
    k_count<<<gE, T, 0, s2>>>(dst, ew, e);          // 1
    k_scan1<<<nScanBlk, 1024, 0, s2>>>(n);          // 2 (+ fused dinv)
    k_gemm<<<GEMM_GRID, 256, GEMM_SMEM>>>(x, W1, g_h_p, n);   // 3  <- profile target
    k_scan2<<<1, 128, 0, s2>>>(nScanBlk, n, e);     // 4
    k_scan3<<<gN, T, 0, s2>>>(n);                   // 5
    k_reorder<<<gE, T, 0, s2>>>(src, dst, ew, e);   // 6
    cudaEventRecord(ev_join, s2);

    cudaStreamWaitEvent(0, ev_join, 0);

    k_agg<<<gW, T>>>(g_h_p, b1, g_z_p, n);
    k_gemm<<<GEMM_GRID, 256, GEMM_SMEM>>>(g_z_p, W2, g_h_p, n);
    k_agg<<<gW, T>>>(g_h_p, b2, out, n);
}